// round 3
// baseline (speedup 1.0000x reference)
#include <cuda_runtime.h>
#include <cuda_bf16.h>
#include <math.h>

#define BS   8
#define SEQ  512
#define C    512
#define NC   5
#define H    768
#define W    768
#define HW   (H*W)             // 589824
#define NTOK (BS*SEQ)          // 4096

// Kernel A geometry: argmax blocks + logits blocks in one heterogeneous grid
#define PX_PER_THREAD 8
#define A_THREADS 256
#define ARG_BLOCKS (BS*HW / PX_PER_THREAD / A_THREADS)   // 2304
#define LOG_BLOCKS (NTOK / 8)                            // 512 (8 warps/block, 1 tok/warp)
#define A_GRID (ARG_BLOCKS + LOG_BLOCKS)                 // 2816

// Kernel B geometry
#define B_THREADS 256
#define B_BLOCKS (NTOK / 8)                              // 512

// Scratch (no allocations allowed)
__device__ unsigned char g_lab[BS * HW];                 // 4.72 MB
__device__ float         g_logits[NTOK * NC];
__device__ float         g_nll[NTOK];
__device__ int           g_msk[NTOK];
__device__ int           g_ctr;                          // zero-init; reset each run

// ---------------------------------------------------------------------------
// Kernel A: heterogeneous grid.
//   blocks [0, ARG_BLOCKS):  per-pixel argmax over NC=5 planes -> uint8 labels
//                            (8 px/thread, streaming float4 loads)
//   blocks [ARG_BLOCKS, ..): per-token logits GEMV (warp per token), runs
//                            concurrently on the FMA pipe while argmax
//                            saturates DRAM.
// ---------------------------------------------------------------------------
__global__ __launch_bounds__(A_THREADS)
void kernelA(const float* __restrict__ cl,
             const float* __restrict__ fuse,
             const float* __restrict__ Wc,
             const float* __restrict__ bc) {
    __shared__ float sW[NC * C];                         // 10 KB (logits path)

    if (blockIdx.x < ARG_BLOCKS) {
        // ---------------- argmax path ----------------
        int g = blockIdx.x * A_THREADS + threadIdx.x;    // thread id over 589,824
        size_t p8 = (size_t)g * PX_PER_THREAD;           // first pixel (8-aligned)
        int b = (int)(p8 / HW);
        size_t off = p8 - (size_t)b * HW;
        const float* base = cl + (size_t)b * NC * HW + off;

        float best[PX_PER_THREAD];
        int   lab[PX_PER_THREAD];

        float4 a0 = __ldcs((const float4*)(base));
        float4 a1 = __ldcs((const float4*)(base + 4));
        best[0]=a0.x; best[1]=a0.y; best[2]=a0.z; best[3]=a0.w;
        best[4]=a1.x; best[5]=a1.y; best[6]=a1.z; best[7]=a1.w;
#pragma unroll
        for (int i = 0; i < 8; ++i) lab[i] = 0;

#pragma unroll
        for (int c = 1; c < NC; ++c) {
            float4 v0 = __ldcs((const float4*)(base + (size_t)c * HW));
            float4 v1 = __ldcs((const float4*)(base + (size_t)c * HW + 4));
            float v[8] = {v0.x,v0.y,v0.z,v0.w,v1.x,v1.y,v1.z,v1.w};
#pragma unroll
            for (int i = 0; i < 8; ++i)
                if (v[i] > best[i]) { best[i] = v[i]; lab[i] = c; }
        }
        // pack 8 labels -> one 8-byte store (p8 is 8-aligned)
        union { unsigned char u8[8]; uint2 u64; } pk;
#pragma unroll
        for (int i = 0; i < 8; ++i) pk.u8[i] = (unsigned char)lab[i];
        *reinterpret_cast<uint2*>(g_lab + p8) = pk.u64;
    } else {
        // ---------------- logits path ----------------
        // stage Wc into shared
        for (int i = threadIdx.x; i < NC * C; i += A_THREADS)
            sW[i] = Wc[i];
        __syncthreads();

        const int warp = threadIdx.x >> 5;
        const int lane = threadIdx.x & 31;
        int t = (blockIdx.x - ARG_BLOCKS) * 8 + warp;    // token id

        const float4* fe4 = reinterpret_cast<const float4*>(fuse + (size_t)t * C);
        const float4* sW4 = reinterpret_cast<const float4*>(sW);

        float acc0=0.f, acc1=0.f, acc2=0.f, acc3=0.f, acc4=0.f;
#pragma unroll
        for (int i = lane; i < C/4; i += 32) {
            float4 e  = fe4[i];
            float4 w0 = sW4[0*(C/4) + i];
            float4 w1 = sW4[1*(C/4) + i];
            float4 w2 = sW4[2*(C/4) + i];
            float4 w3 = sW4[3*(C/4) + i];
            float4 w4 = sW4[4*(C/4) + i];
            acc0 += e.x*w0.x + e.y*w0.y + e.z*w0.z + e.w*w0.w;
            acc1 += e.x*w1.x + e.y*w1.y + e.z*w1.z + e.w*w1.w;
            acc2 += e.x*w2.x + e.y*w2.y + e.z*w2.z + e.w*w2.w;
            acc3 += e.x*w3.x + e.y*w3.y + e.z*w3.z + e.w*w3.w;
            acc4 += e.x*w4.x + e.y*w4.y + e.z*w4.z + e.w*w4.w;
        }
#pragma unroll
        for (int off = 16; off; off >>= 1) {
            acc0 += __shfl_xor_sync(0xffffffffu, acc0, off);
            acc1 += __shfl_xor_sync(0xffffffffu, acc1, off);
            acc2 += __shfl_xor_sync(0xffffffffu, acc2, off);
            acc3 += __shfl_xor_sync(0xffffffffu, acc3, off);
            acc4 += __shfl_xor_sync(0xffffffffu, acc4, off);
        }
        if (lane == 0) {
            g_logits[t*NC + 0] = acc0 + __ldg(bc + 0);
            g_logits[t*NC + 1] = acc1 + __ldg(bc + 1);
            g_logits[t*NC + 2] = acc2 + __ldg(bc + 2);
            g_logits[t*NC + 3] = acc3 + __ldg(bc + 3);
            g_logits[t*NC + 4] = acc4 + __ldg(bc + 4);
        }
    }
}

// ---------------------------------------------------------------------------
// Kernel B: warp per token — box histogram over uint8 label map (L2-resident),
// first-max argmax, NLL from precomputed logits. Last block (atomic counter)
// does the deterministic fixed-order final reduction and writes the scalar.
// ---------------------------------------------------------------------------
__global__ __launch_bounds__(B_THREADS)
void kernelB(const int* __restrict__ coords,
             const int* __restrict__ mask,
             float* __restrict__ out) {
    const int warp = threadIdx.x >> 5;
    const int lane = threadIdx.x & 31;
    int t = blockIdx.x * 8 + warp;
    const int b = t / SEQ;

    int x0 = coords[t*4+0], y0 = coords[t*4+1];
    int x1 = coords[t*4+2], y1 = coords[t*4+3];
    if (y1 == y0) y1 = y0 + 1;
    if (x1 == x0) x1 = x0 + 1;

    int c0=0,c1=0,c2=0,c3=0,c4=0;
    const unsigned char* labb = g_lab + (size_t)b * HW;
    for (int y = y0; y < y1; ++y) {
        const unsigned char* row = labb + (size_t)y * W;
        for (int x = x0 + lane; x < x1; x += 32) {
            int l = row[x];
            c0 += (l==0); c1 += (l==1); c2 += (l==2); c3 += (l==3); c4 += (l==4);
        }
    }
    c0 = __reduce_add_sync(0xffffffffu, c0);
    c1 = __reduce_add_sync(0xffffffffu, c1);
    c2 = __reduce_add_sync(0xffffffffu, c2);
    c3 = __reduce_add_sync(0xffffffffu, c3);
    c4 = __reduce_add_sync(0xffffffffu, c4);

    if (lane == 0) {
        int maj = 0, bestc = c0;
        if (c1 > bestc) { bestc = c1; maj = 1; }
        if (c2 > bestc) { bestc = c2; maj = 2; }
        if (c3 > bestc) { bestc = c3; maj = 3; }
        if (c4 > bestc) { bestc = c4; maj = 4; }

        float lg[NC];
#pragma unroll
        for (int c = 0; c < NC; ++c) lg[c] = g_logits[t*NC + c];
        float mx = lg[0];
#pragma unroll
        for (int c = 1; c < NC; ++c) mx = fmaxf(mx, lg[c]);
        float se = 0.f;
#pragma unroll
        for (int c = 0; c < NC; ++c) se += expf(lg[c] - mx);
        float nll = -(lg[maj] - mx - logf(se));

        int m = (mask[t] == 1) ? 1 : 0;
        g_nll[t] = nll * (float)m;
        g_msk[t] = m;
    }

    // ---- last-block-done deterministic reduction ----
    __shared__ bool s_last;
    __threadfence();
    __syncthreads();
    if (threadIdx.x == 0) {
        int v = atomicAdd(&g_ctr, 1);
        s_last = (v == B_BLOCKS - 1);
    }
    __syncthreads();
    if (!s_last) return;
    __threadfence();   // ensure all blocks' g_nll/g_msk writes are visible

    __shared__ float sf[B_THREADS];
    __shared__ int   si[B_THREADS];
    float a = 0.f; int m = 0;
#pragma unroll
    for (int i = threadIdx.x; i < NTOK; i += B_THREADS) {
        a += g_nll[i]; m += g_msk[i];
    }
    sf[threadIdx.x] = a; si[threadIdx.x] = m;
    __syncthreads();
#pragma unroll
    for (int s = B_THREADS/2; s > 0; s >>= 1) {
        if (threadIdx.x < s) { sf[threadIdx.x] += sf[threadIdx.x+s];
                               si[threadIdx.x] += si[threadIdx.x+s]; }
        __syncthreads();
    }
    if (threadIdx.x == 0) {
        out[0] = sf[0] / (float)si[0];
        g_ctr = 0;   // reset for next (graph-replayed) run
    }
}

extern "C" void kernel_launch(void* const* d_in, const int* in_sizes, int n_in,
                              void* d_out, int out_size) {
    const float* fuse   = (const float*)d_in[0];   // [8,512,512]
    const float* cl     = (const float*)d_in[1];   // [8,5,768,768]
    const float* Wc     = (const float*)d_in[2];   // [5,512]
    const float* bc     = (const float*)d_in[3];   // [5]
    const int*   coords = (const int*)d_in[4];     // [8,512,4]
    const int*   mask   = (const int*)d_in[5];     // [8,512]
    float* out = (float*)d_out;

    kernelA<<<A_GRID, A_THREADS>>>(cl, fuse, Wc, bc);
    kernelB<<<B_BLOCKS, B_THREADS>>>(coords, mask, out);
}

// round 4
// speedup vs baseline: 1.5804x; 1.5804x over previous
#include <cuda_runtime.h>
#include <cuda_bf16.h>
#include <math.h>

#define BS   8
#define SEQ  512
#define C    512
#define NC   5
#define H    768
#define W    768
#define HW   (H*W)
#define NTOK (BS*SEQ)          // 4096

#define T_THREADS 256
#define T_BLOCKS  (NTOK / 8)   // 512 (8 warps/block, 1 token/warp)

// Scratch (no allocations allowed)
__device__ unsigned char g_lab[BS * HW];   // 4.72 MB label map
__device__ float         g_nll[NTOK];
__device__ int           g_msk[NTOK];
__device__ int           g_ctr;            // zero-init; reset at end of each run

// ---------------------------------------------------------------------------
// Kernel 1 (EXACT round-1 version — measured 17.2us @ 72% DRAM):
// per-pixel argmax over NC=5 channel planes -> uint8 labels, 4 px/thread.
// ---------------------------------------------------------------------------
__global__ void argmax_labels_kernel(const float* __restrict__ cl) {
    const int n4 = BS * HW / 4;
    int g = blockIdx.x * blockDim.x + threadIdx.x;
    if (g >= n4) return;

    const int pix_per_img4 = HW / 4;
    int b = g / pix_per_img4;
    int p4 = g - b * pix_per_img4;
    size_t base = (size_t)b * NC * HW + (size_t)p4 * 4;

    float best0, best1, best2, best3;
    int   lab0 = 0, lab1 = 0, lab2 = 0, lab3 = 0;
    {
        float4 v = *reinterpret_cast<const float4*>(cl + base);
        best0 = v.x; best1 = v.y; best2 = v.z; best3 = v.w;
    }
#pragma unroll
    for (int c = 1; c < NC; ++c) {
        float4 v = *reinterpret_cast<const float4*>(cl + base + (size_t)c * HW);
        if (v.x > best0) { best0 = v.x; lab0 = c; }
        if (v.y > best1) { best1 = v.y; lab1 = c; }
        if (v.z > best2) { best2 = v.z; lab2 = c; }
        if (v.w > best3) { best3 = v.w; lab3 = c; }
    }
    uchar4 out;
    out.x = (unsigned char)lab0; out.y = (unsigned char)lab1;
    out.z = (unsigned char)lab2; out.w = (unsigned char)lab3;
    *reinterpret_cast<uchar4*>(g_lab + (size_t)b * HW + (size_t)p4 * 4) = out;
}

// ---------------------------------------------------------------------------
// Kernel 2: one warp per token.
//  - logits[5] via warp GEMV (Wc staged in shared)
//  - box histogram via aligned uint32 loads + __vcmpeq4/__popc SIMD counting
//    (edge bytes forced to 0xFF = matches no class; class4 = area - others)
//  - first-max argmax (bincount tiebreak), masked NLL
//  - last block does the deterministic fixed-order final reduction
// ---------------------------------------------------------------------------
__global__ __launch_bounds__(T_THREADS)
void token_kernel(const float* __restrict__ fuse,
                  const float* __restrict__ Wc,
                  const float* __restrict__ bc,
                  const int*   __restrict__ coords,
                  const int*   __restrict__ mask,
                  float* __restrict__ out) {
    __shared__ float sW[NC * C];                 // 10 KB
    for (int i = threadIdx.x; i < NC * C; i += T_THREADS)
        sW[i] = Wc[i];
    __syncthreads();

    const int warp = threadIdx.x >> 5;
    const int lane = threadIdx.x & 31;
    const int t = blockIdx.x * 8 + warp;         // token id
    const int b = t / SEQ;

    // ---- logits (warp GEMV, float4) ----
    const float4* fe4 = reinterpret_cast<const float4*>(fuse + (size_t)t * C);
    const float4* sW4 = reinterpret_cast<const float4*>(sW);
    float acc0=0.f, acc1=0.f, acc2=0.f, acc3=0.f, acc4=0.f;
#pragma unroll
    for (int i = lane; i < C/4; i += 32) {
        float4 e  = fe4[i];
        float4 w0 = sW4[0*(C/4) + i];
        float4 w1 = sW4[1*(C/4) + i];
        float4 w2 = sW4[2*(C/4) + i];
        float4 w3 = sW4[3*(C/4) + i];
        float4 w4 = sW4[4*(C/4) + i];
        acc0 += e.x*w0.x + e.y*w0.y + e.z*w0.z + e.w*w0.w;
        acc1 += e.x*w1.x + e.y*w1.y + e.z*w1.z + e.w*w1.w;
        acc2 += e.x*w2.x + e.y*w2.y + e.z*w2.z + e.w*w2.w;
        acc3 += e.x*w3.x + e.y*w3.y + e.z*w3.z + e.w*w3.w;
        acc4 += e.x*w4.x + e.y*w4.y + e.z*w4.z + e.w*w4.w;
    }
#pragma unroll
    for (int off = 16; off; off >>= 1) {
        acc0 += __shfl_xor_sync(0xffffffffu, acc0, off);
        acc1 += __shfl_xor_sync(0xffffffffu, acc1, off);
        acc2 += __shfl_xor_sync(0xffffffffu, acc2, off);
        acc3 += __shfl_xor_sync(0xffffffffu, acc3, off);
        acc4 += __shfl_xor_sync(0xffffffffu, acc4, off);
    }

    // ---- box histogram (word loads + SIMD byte count) ----
    int x0 = coords[t*4+0], y0 = coords[t*4+1];
    int x1 = coords[t*4+2], y1 = coords[t*4+3];
    if (y1 == y0) y1 = y0 + 1;
    if (x1 == x0) x1 = x0 + 1;

    const int wx0  = x0 >> 2;
    const int wx1  = (x1 + 3) >> 2;          // exclusive
    const int wpr  = wx1 - wx0;              // words per row (<=17)
    const int rows = y1 - y0;
    const int nidx = rows * wpr;             // flattened (row, word) space

    // edge masks: 0xFF bytes for pixels outside [x0, x1)
    const int kf = x0 & 3;
    const unsigned mfirst = kf ? ((1u << (8*kf)) - 1u) : 0u;
    const int x1e = x1 - 4*(wx1 - 1);        // 1..4 valid bytes in last word
    const unsigned mlast = (x1e == 4) ? 0u : ~((1u << (8*x1e)) - 1u);

    const unsigned char* labb = g_lab + (size_t)b * HW;
    int p0=0, p1=0, p2=0, p3=0;              // popc sums (x8)
    for (int idx = lane; idx < nidx; idx += 32) {
        int ry = idx / wpr;
        int wx = wx0 + (idx - ry * wpr);
        unsigned u = *reinterpret_cast<const unsigned*>(
            labb + (size_t)(y0 + ry) * W + (size_t)wx * 4);
        unsigned inv = 0u;
        if (wx == wx0)     inv |= mfirst;
        if (wx == wx1 - 1) inv |= mlast;
        u |= inv;                             // invalid bytes -> 0xFF (no class)
        p0 += __popc(__vcmpeq4(u, 0x00000000u));
        p1 += __popc(__vcmpeq4(u, 0x01010101u));
        p2 += __popc(__vcmpeq4(u, 0x02020202u));
        p3 += __popc(__vcmpeq4(u, 0x03030303u));
    }
    p0 = __reduce_add_sync(0xffffffffu, p0);
    p1 = __reduce_add_sync(0xffffffffu, p1);
    p2 = __reduce_add_sync(0xffffffffu, p2);
    p3 = __reduce_add_sync(0xffffffffu, p3);

    if (lane == 0) {
        int c0 = p0 >> 3, c1 = p1 >> 3, c2 = p2 >> 3, c3 = p3 >> 3;
        int c4 = rows * (x1 - x0) - c0 - c1 - c2 - c3;

        int maj = 0, bestc = c0;
        if (c1 > bestc) { bestc = c1; maj = 1; }
        if (c2 > bestc) { bestc = c2; maj = 2; }
        if (c3 > bestc) { bestc = c3; maj = 3; }
        if (c4 > bestc) { bestc = c4; maj = 4; }

        float lg[NC];
        lg[0] = acc0 + bc[0]; lg[1] = acc1 + bc[1]; lg[2] = acc2 + bc[2];
        lg[3] = acc3 + bc[3]; lg[4] = acc4 + bc[4];
        float mx = lg[0];
#pragma unroll
        for (int c = 1; c < NC; ++c) mx = fmaxf(mx, lg[c]);
        float se = 0.f;
#pragma unroll
        for (int c = 0; c < NC; ++c) se += expf(lg[c] - mx);
        float nll = -(lg[maj] - mx - logf(se));

        int m = (mask[t] == 1) ? 1 : 0;
        g_nll[t] = nll * (float)m;
        g_msk[t] = m;
    }

    // ---- last-block-done deterministic reduction ----
    __shared__ bool s_last;
    __threadfence();
    __syncthreads();
    if (threadIdx.x == 0) {
        int v = atomicAdd(&g_ctr, 1);
        s_last = (v == T_BLOCKS - 1);
    }
    __syncthreads();
    if (!s_last) return;
    __threadfence();

    __shared__ float sf[T_THREADS];
    __shared__ int   si[T_THREADS];
    float a = 0.f; int m = 0;
#pragma unroll
    for (int i = threadIdx.x; i < NTOK; i += T_THREADS) {
        a += g_nll[i]; m += g_msk[i];
    }
    sf[threadIdx.x] = a; si[threadIdx.x] = m;
    __syncthreads();
#pragma unroll
    for (int s = T_THREADS/2; s > 0; s >>= 1) {
        if (threadIdx.x < s) { sf[threadIdx.x] += sf[threadIdx.x+s];
                               si[threadIdx.x] += si[threadIdx.x+s]; }
        __syncthreads();
    }
    if (threadIdx.x == 0) {
        out[0] = sf[0] / (float)si[0];
        g_ctr = 0;
    }
}

extern "C" void kernel_launch(void* const* d_in, const int* in_sizes, int n_in,
                              void* d_out, int out_size) {
    const float* fuse   = (const float*)d_in[0];   // [8,512,512]
    const float* cl     = (const float*)d_in[1];   // [8,5,768,768]
    const float* Wc     = (const float*)d_in[2];   // [5,512]
    const float* bc     = (const float*)d_in[3];   // [5]
    const int*   coords = (const int*)d_in[4];     // [8,512,4]
    const int*   mask   = (const int*)d_in[5];     // [8,512]
    float* out = (float*)d_out;

    {
        int n4 = BS * HW / 4;
        int threads = 256;
        int blocks = (n4 + threads - 1) / threads;
        argmax_labels_kernel<<<blocks, threads>>>(cl);
    }
    token_kernel<<<T_BLOCKS, T_THREADS>>>(fuse, Wc, bc, coords, mask, out);
}

// round 5
// speedup vs baseline: 1.7413x; 1.1018x over previous
#include <cuda_runtime.h>
#include <cuda_bf16.h>
#include <math.h>

#define BS   8
#define SEQ  512
#define C    512
#define NC   5
#define H    768
#define W    768
#define HW   (H*W)
#define NTOK (BS*SEQ)          // 4096

#define THREADS 256
#define GRID    592            // 148 SMs x 4 blocks; co-resident by __launch_bounds__(256,4)

// Scratch (no allocations allowed)
__device__ unsigned char g_lab[BS * HW];   // 4.72 MB label map
__device__ float         g_nll[NTOK];
__device__ int           g_msk[NTOK];
__device__ int           g_bar;            // grid barrier counter (zero-init, reset each run)
__device__ int           g_ctr;            // completion counter  (zero-init, reset each run)

// ---------------------------------------------------------------------------
// ONE persistent kernel:
//   phase A: grid-stride per-pixel argmax (NC=5) -> uint8 label map
//   phase B: warp-per-token logits GEMV (independent of labels; overlaps
//            argmax stragglers; logits stay in registers)
//   software grid barrier (all 592 blocks guaranteed co-resident)
//   phase C: box histogram over L2-hot label map (uint32 + SIMD byte count),
//            first-max argmax, masked NLL
//   phase D: last block does deterministic fixed-order reduction, resets state
// ---------------------------------------------------------------------------
__global__ __launch_bounds__(THREADS, 4)
void fused_kernel(const float* __restrict__ cl,
                  const float* __restrict__ fuse,
                  const float* __restrict__ Wc,
                  const float* __restrict__ bc,
                  const int*   __restrict__ coords,
                  const int*   __restrict__ mask,
                  float* __restrict__ out) {
    __shared__ float sW[NC * C];                 // 10 KB
    for (int i = threadIdx.x; i < NC * C; i += THREADS)
        sW[i] = Wc[i];

    // ---------------- phase A: argmax label map (grid-stride) ----------------
    const int n4 = BS * HW / 4;
    const int pix_per_img4 = HW / 4;
    for (int g = blockIdx.x * THREADS + threadIdx.x; g < n4; g += GRID * THREADS) {
        int b  = g / pix_per_img4;
        int p4 = g - b * pix_per_img4;
        size_t base = (size_t)b * NC * HW + (size_t)p4 * 4;

        float best0, best1, best2, best3;
        int   lab0 = 0, lab1 = 0, lab2 = 0, lab3 = 0;
        {
            float4 v = *reinterpret_cast<const float4*>(cl + base);
            best0 = v.x; best1 = v.y; best2 = v.z; best3 = v.w;
        }
#pragma unroll
        for (int c = 1; c < NC; ++c) {
            float4 v = *reinterpret_cast<const float4*>(cl + base + (size_t)c * HW);
            if (v.x > best0) { best0 = v.x; lab0 = c; }
            if (v.y > best1) { best1 = v.y; lab1 = c; }
            if (v.z > best2) { best2 = v.z; lab2 = c; }
            if (v.w > best3) { best3 = v.w; lab3 = c; }
        }
        uchar4 o;
        o.x = (unsigned char)lab0; o.y = (unsigned char)lab1;
        o.z = (unsigned char)lab2; o.w = (unsigned char)lab3;
        *reinterpret_cast<uchar4*>(g_lab + (size_t)b * HW + (size_t)p4 * 4) = o;
    }

    // ---------------- phase B: logits GEMV (no label dependency) -------------
    __syncthreads();                             // sW staged
    const int warp = threadIdx.x >> 5;
    const int lane = threadIdx.x & 31;
    const int t = blockIdx.x * 8 + warp;         // token id (some warps idle)

    float acc0 = 0.f, acc1 = 0.f, acc2 = 0.f, acc3 = 0.f, acc4 = 0.f;
    if (t < NTOK) {
        const float4* fe4 = reinterpret_cast<const float4*>(fuse + (size_t)t * C);
        const float4* sW4 = reinterpret_cast<const float4*>(sW);
#pragma unroll
        for (int i = lane; i < C/4; i += 32) {
            float4 e  = fe4[i];
            float4 w0 = sW4[0*(C/4) + i];
            float4 w1 = sW4[1*(C/4) + i];
            float4 w2 = sW4[2*(C/4) + i];
            float4 w3 = sW4[3*(C/4) + i];
            float4 w4 = sW4[4*(C/4) + i];
            acc0 += e.x*w0.x + e.y*w0.y + e.z*w0.z + e.w*w0.w;
            acc1 += e.x*w1.x + e.y*w1.y + e.z*w1.z + e.w*w1.w;
            acc2 += e.x*w2.x + e.y*w2.y + e.z*w2.z + e.w*w2.w;
            acc3 += e.x*w3.x + e.y*w3.y + e.z*w3.z + e.w*w3.w;
            acc4 += e.x*w4.x + e.y*w4.y + e.z*w4.z + e.w*w4.w;
        }
#pragma unroll
        for (int off = 16; off; off >>= 1) {
            acc0 += __shfl_xor_sync(0xffffffffu, acc0, off);
            acc1 += __shfl_xor_sync(0xffffffffu, acc1, off);
            acc2 += __shfl_xor_sync(0xffffffffu, acc2, off);
            acc3 += __shfl_xor_sync(0xffffffffu, acc3, off);
            acc4 += __shfl_xor_sync(0xffffffffu, acc4, off);
        }
    }

    // ---------------- software grid barrier ----------------
    __syncthreads();                             // all block stores to g_lab issued
    __threadfence();                             // ... and visible device-wide
    if (threadIdx.x == 0) {
        atomicAdd(&g_bar, 1);
        while (atomicAdd(&g_bar, 0) < GRID) __nanosleep(64);
    }
    __syncthreads();
    __threadfence();

    // ---------------- phase C: box histogram + NLL ----------------
    if (t < NTOK) {
        const int b = t / SEQ;
        int x0 = coords[t*4+0], y0 = coords[t*4+1];
        int x1 = coords[t*4+2], y1 = coords[t*4+3];
        if (y1 == y0) y1 = y0 + 1;
        if (x1 == x0) x1 = x0 + 1;

        const int wx0  = x0 >> 2;
        const int wx1  = (x1 + 3) >> 2;          // exclusive
        const int wpr  = wx1 - wx0;              // words per row (<=17)
        const int rows = y1 - y0;
        const int nidx = rows * wpr;

        const int kf = x0 & 3;
        const unsigned mfirst = kf ? ((1u << (8*kf)) - 1u) : 0u;
        const int x1e = x1 - 4*(wx1 - 1);        // 1..4 valid bytes in last word
        const unsigned mlast = (x1e == 4) ? 0u : ~((1u << (8*x1e)) - 1u);

        const unsigned char* labb = g_lab + (size_t)b * HW;
        int p0=0, p1=0, p2=0, p3=0;              // popc sums (x8)
        for (int idx = lane; idx < nidx; idx += 32) {
            int ry = idx / wpr;
            int wx = wx0 + (idx - ry * wpr);
            unsigned u = *reinterpret_cast<const unsigned*>(
                labb + (size_t)(y0 + ry) * W + (size_t)wx * 4);
            unsigned inv = 0u;
            if (wx == wx0)     inv |= mfirst;
            if (wx == wx1 - 1) inv |= mlast;
            u |= inv;                            // invalid bytes -> 0xFF (no class)
            p0 += __popc(__vcmpeq4(u, 0x00000000u));
            p1 += __popc(__vcmpeq4(u, 0x01010101u));
            p2 += __popc(__vcmpeq4(u, 0x02020202u));
            p3 += __popc(__vcmpeq4(u, 0x03030303u));
        }
        p0 = __reduce_add_sync(0xffffffffu, p0);
        p1 = __reduce_add_sync(0xffffffffu, p1);
        p2 = __reduce_add_sync(0xffffffffu, p2);
        p3 = __reduce_add_sync(0xffffffffu, p3);

        if (lane == 0) {
            int c0 = p0 >> 3, c1 = p1 >> 3, c2 = p2 >> 3, c3 = p3 >> 3;
            int c4 = rows * (x1 - x0) - c0 - c1 - c2 - c3;

            int maj = 0, bestc = c0;
            if (c1 > bestc) { bestc = c1; maj = 1; }
            if (c2 > bestc) { bestc = c2; maj = 2; }
            if (c3 > bestc) { bestc = c3; maj = 3; }
            if (c4 > bestc) { bestc = c4; maj = 4; }

            float lg[NC];
            lg[0] = acc0 + bc[0]; lg[1] = acc1 + bc[1]; lg[2] = acc2 + bc[2];
            lg[3] = acc3 + bc[3]; lg[4] = acc4 + bc[4];
            float mx = lg[0];
#pragma unroll
            for (int c = 1; c < NC; ++c) mx = fmaxf(mx, lg[c]);
            float se = 0.f;
#pragma unroll
            for (int c = 0; c < NC; ++c) se += expf(lg[c] - mx);
            float nll = -(lg[maj] - mx - logf(se));

            int m = (mask[t] == 1) ? 1 : 0;
            g_nll[t] = nll * (float)m;
            g_msk[t] = m;
        }
    }

    // ---------------- phase D: last-block deterministic reduction ------------
    __shared__ bool s_last;
    __syncthreads();
    __threadfence();
    if (threadIdx.x == 0) {
        s_last = (atomicAdd(&g_ctr, 1) == GRID - 1);
    }
    __syncthreads();
    if (!s_last) return;
    __threadfence();

    __shared__ float sf[THREADS];
    __shared__ int   si[THREADS];
    float a = 0.f; int m = 0;
#pragma unroll
    for (int i = threadIdx.x; i < NTOK; i += THREADS) {
        a += g_nll[i]; m += g_msk[i];
    }
    sf[threadIdx.x] = a; si[threadIdx.x] = m;
    __syncthreads();
#pragma unroll
    for (int s = THREADS/2; s > 0; s >>= 1) {
        if (threadIdx.x < s) { sf[threadIdx.x] += sf[threadIdx.x+s];
                               si[threadIdx.x] += si[threadIdx.x+s]; }
        __syncthreads();
    }
    if (threadIdx.x == 0) {
        out[0] = sf[0] / (float)si[0];
        g_ctr = 0;                 // reset state for next graph replay
        g_bar = 0;
    }
}

extern "C" void kernel_launch(void* const* d_in, const int* in_sizes, int n_in,
                              void* d_out, int out_size) {
    const float* fuse   = (const float*)d_in[0];   // [8,512,512]
    const float* cl     = (const float*)d_in[1];   // [8,5,768,768]
    const float* Wc     = (const float*)d_in[2];   // [5,512]
    const float* bc     = (const float*)d_in[3];   // [5]
    const int*   coords = (const int*)d_in[4];     // [8,512,4]
    const int*   mask   = (const int*)d_in[5];     // [8,512]
    float* out = (float*)d_out;

    fused_kernel<<<GRID, THREADS>>>(cl, fuse, Wc, bc, coords, mask, out);
}

// round 6
// speedup vs baseline: 1.8382x; 1.0556x over previous
#include <cuda_runtime.h>
#include <cuda_bf16.h>
#include <math.h>

#define BS   8
#define SEQ  512
#define C    512
#define NC   5
#define H    768
#define W    768
#define HW   (H*W)
#define NTOK (BS*SEQ)          // 4096

#define THREADS 256
#define BLOCKS_PER_SM 6
#define GRID    (148 * BLOCKS_PER_SM)   // 888; co-resident by __launch_bounds__

// Scratch (no allocations allowed)
__device__ unsigned char g_lab[BS * HW];   // 4.72 MB label map
__device__ float         g_nll[NTOK];
__device__ int           g_msk[NTOK];
__device__ int           g_bar;            // grid barrier counter (zero-init, reset each run)
__device__ int           g_ctr;            // completion counter  (zero-init, reset each run)

// ---------------------------------------------------------------------------
// ONE persistent kernel (6 blocks/SM for phase-A DRAM occupancy):
//   phase A: grid-stride per-pixel argmax (NC=5) -> uint8 label map
//   phase B: warp-per-token logits GEMV (independent of labels)
//   software grid barrier (all 888 blocks co-resident)
//   phase C: box histogram over L2-hot label map (uint32 + SIMD byte count),
//            first-max argmax, masked NLL
//   phase D: last block does deterministic fixed-order reduction, resets state
// ---------------------------------------------------------------------------
__global__ __launch_bounds__(THREADS, BLOCKS_PER_SM)
void fused_kernel(const float* __restrict__ cl,
                  const float* __restrict__ fuse,
                  const float* __restrict__ Wc,
                  const float* __restrict__ bc,
                  const int*   __restrict__ coords,
                  const int*   __restrict__ mask,
                  float* __restrict__ out) {
    __shared__ float sW[NC * C];                 // 10 KB
    for (int i = threadIdx.x; i < NC * C; i += THREADS)
        sW[i] = Wc[i];

    // ---------------- phase A: argmax label map (grid-stride) ----------------
    const int n4 = BS * HW / 4;
    const int pix_per_img4 = HW / 4;
    for (int g = blockIdx.x * THREADS + threadIdx.x; g < n4; g += GRID * THREADS) {
        int b  = g / pix_per_img4;
        int p4 = g - b * pix_per_img4;
        size_t base = (size_t)b * NC * HW + (size_t)p4 * 4;

        float best0, best1, best2, best3;
        int   lab0 = 0, lab1 = 0, lab2 = 0, lab3 = 0;
        {
            float4 v = *reinterpret_cast<const float4*>(cl + base);
            best0 = v.x; best1 = v.y; best2 = v.z; best3 = v.w;
        }
#pragma unroll
        for (int c = 1; c < NC; ++c) {
            float4 v = *reinterpret_cast<const float4*>(cl + base + (size_t)c * HW);
            if (v.x > best0) { best0 = v.x; lab0 = c; }
            if (v.y > best1) { best1 = v.y; lab1 = c; }
            if (v.z > best2) { best2 = v.z; lab2 = c; }
            if (v.w > best3) { best3 = v.w; lab3 = c; }
        }
        uchar4 o;
        o.x = (unsigned char)lab0; o.y = (unsigned char)lab1;
        o.z = (unsigned char)lab2; o.w = (unsigned char)lab3;
        *reinterpret_cast<uchar4*>(g_lab + (size_t)b * HW + (size_t)p4 * 4) = o;
    }

    // ---------------- phase B: logits GEMV (no label dependency) -------------
    __syncthreads();                             // sW staged
    const int warp = threadIdx.x >> 5;
    const int lane = threadIdx.x & 31;
    const int t = blockIdx.x * 8 + warp;         // token id (blocks >=512 idle here)

    float acc0 = 0.f, acc1 = 0.f, acc2 = 0.f, acc3 = 0.f, acc4 = 0.f;
    if (t < NTOK) {
        const float4* fe4 = reinterpret_cast<const float4*>(fuse + (size_t)t * C);
        const float4* sW4 = reinterpret_cast<const float4*>(sW);
#pragma unroll
        for (int i = lane; i < C/4; i += 32) {
            float4 e  = fe4[i];
            float4 w0 = sW4[0*(C/4) + i];
            float4 w1 = sW4[1*(C/4) + i];
            float4 w2 = sW4[2*(C/4) + i];
            float4 w3 = sW4[3*(C/4) + i];
            float4 w4 = sW4[4*(C/4) + i];
            acc0 += e.x*w0.x + e.y*w0.y + e.z*w0.z + e.w*w0.w;
            acc1 += e.x*w1.x + e.y*w1.y + e.z*w1.z + e.w*w1.w;
            acc2 += e.x*w2.x + e.y*w2.y + e.z*w2.z + e.w*w2.w;
            acc3 += e.x*w3.x + e.y*w3.y + e.z*w3.z + e.w*w3.w;
            acc4 += e.x*w4.x + e.y*w4.y + e.z*w4.z + e.w*w4.w;
        }
#pragma unroll
        for (int off = 16; off; off >>= 1) {
            acc0 += __shfl_xor_sync(0xffffffffu, acc0, off);
            acc1 += __shfl_xor_sync(0xffffffffu, acc1, off);
            acc2 += __shfl_xor_sync(0xffffffffu, acc2, off);
            acc3 += __shfl_xor_sync(0xffffffffu, acc3, off);
            acc4 += __shfl_xor_sync(0xffffffffu, acc4, off);
        }
    }

    // ---------------- software grid barrier ----------------
    __syncthreads();                             // all block stores to g_lab issued
    __threadfence();                             // ... and visible device-wide
    if (threadIdx.x == 0) {
        atomicAdd(&g_bar, 1);
        while (atomicAdd(&g_bar, 0) < GRID) __nanosleep(64);
    }
    __syncthreads();
    __threadfence();

    // ---------------- phase C: box histogram + NLL ----------------
    if (t < NTOK) {
        const int b = t / SEQ;
        int x0 = coords[t*4+0], y0 = coords[t*4+1];
        int x1 = coords[t*4+2], y1 = coords[t*4+3];
        if (y1 == y0) y1 = y0 + 1;
        if (x1 == x0) x1 = x0 + 1;

        const int wx0  = x0 >> 2;
        const int wx1  = (x1 + 3) >> 2;          // exclusive
        const int wpr  = wx1 - wx0;              // words per row (<=17)
        const int rows = y1 - y0;
        const int nidx = rows * wpr;

        const int kf = x0 & 3;
        const unsigned mfirst = kf ? ((1u << (8*kf)) - 1u) : 0u;
        const int x1e = x1 - 4*(wx1 - 1);        // 1..4 valid bytes in last word
        const unsigned mlast = (x1e == 4) ? 0u : ~((1u << (8*x1e)) - 1u);

        const unsigned char* labb = g_lab + (size_t)b * HW;
        int p0=0, p1=0, p2=0, p3=0;              // popc sums (x8)
        for (int idx = lane; idx < nidx; idx += 32) {
            int ry = idx / wpr;
            int wx = wx0 + (idx - ry * wpr);
            unsigned u = *reinterpret_cast<const unsigned*>(
                labb + (size_t)(y0 + ry) * W + (size_t)wx * 4);
            unsigned inv = 0u;
            if (wx == wx0)     inv |= mfirst;
            if (wx == wx1 - 1) inv |= mlast;
            u |= inv;                            // invalid bytes -> 0xFF (no class)
            p0 += __popc(__vcmpeq4(u, 0x00000000u));
            p1 += __popc(__vcmpeq4(u, 0x01010101u));
            p2 += __popc(__vcmpeq4(u, 0x02020202u));
            p3 += __popc(__vcmpeq4(u, 0x03030303u));
        }
        p0 = __reduce_add_sync(0xffffffffu, p0);
        p1 = __reduce_add_sync(0xffffffffu, p1);
        p2 = __reduce_add_sync(0xffffffffu, p2);
        p3 = __reduce_add_sync(0xffffffffu, p3);

        if (lane == 0) {
            int c0 = p0 >> 3, c1 = p1 >> 3, c2 = p2 >> 3, c3 = p3 >> 3;
            int c4 = rows * (x1 - x0) - c0 - c1 - c2 - c3;

            int maj = 0, bestc = c0;
            if (c1 > bestc) { bestc = c1; maj = 1; }
            if (c2 > bestc) { bestc = c2; maj = 2; }
            if (c3 > bestc) { bestc = c3; maj = 3; }
            if (c4 > bestc) { bestc = c4; maj = 4; }

            float lg[NC];
            lg[0] = acc0 + bc[0]; lg[1] = acc1 + bc[1]; lg[2] = acc2 + bc[2];
            lg[3] = acc3 + bc[3]; lg[4] = acc4 + bc[4];
            float mx = lg[0];
#pragma unroll
            for (int c = 1; c < NC; ++c) mx = fmaxf(mx, lg[c]);
            float se = 0.f;
#pragma unroll
            for (int c = 0; c < NC; ++c) se += expf(lg[c] - mx);
            float nll = -(lg[maj] - mx - logf(se));

            int m = (mask[t] == 1) ? 1 : 0;
            g_nll[t] = nll * (float)m;
            g_msk[t] = m;
        }
    }

    // ---------------- phase D: last-block deterministic reduction ------------
    __shared__ bool s_last;
    __syncthreads();
    __threadfence();
    if (threadIdx.x == 0) {
        s_last = (atomicAdd(&g_ctr, 1) == GRID - 1);
    }
    __syncthreads();
    if (!s_last) return;
    __threadfence();

    __shared__ float sf[THREADS];
    __shared__ int   si[THREADS];
    float a = 0.f; int m = 0;
#pragma unroll
    for (int i = threadIdx.x; i < NTOK; i += THREADS) {
        a += g_nll[i]; m += g_msk[i];
    }
    sf[threadIdx.x] = a; si[threadIdx.x] = m;
    __syncthreads();
#pragma unroll
    for (int s = THREADS/2; s > 0; s >>= 1) {
        if (threadIdx.x < s) { sf[threadIdx.x] += sf[threadIdx.x+s];
                               si[threadIdx.x] += si[threadIdx.x+s]; }
        __syncthreads();
    }
    if (threadIdx.x == 0) {
        out[0] = sf[0] / (float)si[0];
        g_ctr = 0;                 // reset state for next graph replay
        g_bar = 0;
    }
}

extern "C" void kernel_launch(void* const* d_in, const int* in_sizes, int n_in,
                              void* d_out, int out_size) {
    const float* fuse   = (const float*)d_in[0];   // [8,512,512]
    const float* cl     = (const float*)d_in[1];   // [8,5,768,768]
    const float* Wc     = (const float*)d_in[2];   // [5,512]
    const float* bc     = (const float*)d_in[3];   // [5]
    const int*   coords = (const int*)d_in[4];     // [8,512,4]
    const int*   mask   = (const int*)d_in[5];     // [8,512]
    float* out = (float*)d_out;

    fused_kernel<<<GRID, THREADS>>>(cl, fuse, Wc, bc, coords, mask, out);
}

// round 7
// speedup vs baseline: 2.0194x; 1.0986x over previous
#include <cuda_runtime.h>
#include <cuda_bf16.h>
#include <math.h>

#define BS   8
#define SEQ  512
#define C    512
#define NC   5
#define H    768
#define W    768
#define HW   (H*W)
#define NTOK (BS*SEQ)          // 4096

#define THREADS 256
#define BLOCKS_PER_SM 6
#define GRID    (148 * BLOCKS_PER_SM)   // 888 = 8 * 111; co-resident
#define BLK_PER_IMG 111                  // argmax producer blocks per image
#define TOK_BLOCKS  (NTOK / 8)           // 512 token blocks (8 warps = 8 tokens each)

// Scratch (no allocations allowed)
__device__ unsigned char g_lab[BS * HW];   // 4.72 MB label map
__device__ float         g_nll[NTOK];
__device__ int           g_msk[NTOK];
__device__ int           g_bar8[BS];       // per-image arrival counters (zero-init)
__device__ int           g_ctr;            // completion counter (zero-init)

// ---------------------------------------------------------------------------
// ONE persistent kernel, per-image dependency tracking:
//   phase A: block j argmaxes a stripe of image j/111 -> uint8 labels
//   arrive:  atomicAdd on that image's counter (no polling with atomics!)
//   phase B: warp-per-token logits GEMV (overlaps other blocks' waits)
//   wait:    token blocks poll THEIR image's counter with volatile LOADS
//   phase C: box histogram (uint32 + SIMD byte count), argmax, masked NLL
//   phase D: last block does deterministic fixed-order reduction, resets state
// ---------------------------------------------------------------------------
__global__ __launch_bounds__(THREADS, BLOCKS_PER_SM)
void fused_kernel(const float* __restrict__ cl,
                  const float* __restrict__ fuse,
                  const float* __restrict__ Wc,
                  const float* __restrict__ bc,
                  const int*   __restrict__ coords,
                  const int*   __restrict__ mask,
                  float* __restrict__ out) {
    __shared__ float sW[NC * C];                 // 10 KB
    for (int i = threadIdx.x; i < NC * C; i += THREADS)
        sW[i] = Wc[i];

    const int j      = blockIdx.x;
    const int my_img = j / BLK_PER_IMG;          // image this block produces
    const int k      = j - my_img * BLK_PER_IMG;

    // ---------------- phase A: argmax stripe of image my_img ----------------
    {
        const int wg = HW / 4;                   // 147,456 word-groups / image
        const float* clb = cl + (size_t)my_img * NC * HW;
        unsigned char* labbase = g_lab + (size_t)my_img * HW;
        for (int g = k * THREADS + threadIdx.x; g < wg; g += BLK_PER_IMG * THREADS) {
            size_t base = (size_t)g * 4;

            float best0, best1, best2, best3;
            int   lab0 = 0, lab1 = 0, lab2 = 0, lab3 = 0;
            {
                float4 v = *reinterpret_cast<const float4*>(clb + base);
                best0 = v.x; best1 = v.y; best2 = v.z; best3 = v.w;
            }
#pragma unroll
            for (int c = 1; c < NC; ++c) {
                float4 v = *reinterpret_cast<const float4*>(clb + base + (size_t)c * HW);
                if (v.x > best0) { best0 = v.x; lab0 = c; }
                if (v.y > best1) { best1 = v.y; lab1 = c; }
                if (v.z > best2) { best2 = v.z; lab2 = c; }
                if (v.w > best3) { best3 = v.w; lab3 = c; }
            }
            uchar4 o;
            o.x = (unsigned char)lab0; o.y = (unsigned char)lab1;
            o.z = (unsigned char)lab2; o.w = (unsigned char)lab3;
            *reinterpret_cast<uchar4*>(labbase + base) = o;
        }
    }

    // ---------------- arrive on my image's counter ----------------
    __threadfence();                             // my stores visible device-wide
    __syncthreads();                             // whole block done storing
    if (threadIdx.x == 0)
        atomicAdd(&g_bar8[my_img], 1);

    // ---------------- phase B: logits GEMV (no label dependency) ------------
    const int warp = threadIdx.x >> 5;
    const int lane = threadIdx.x & 31;
    const int t = j * 8 + warp;                  // token id (blocks >=512 idle)

    float acc0 = 0.f, acc1 = 0.f, acc2 = 0.f, acc3 = 0.f, acc4 = 0.f;
    if (t < NTOK) {
        const float4* fe4 = reinterpret_cast<const float4*>(fuse + (size_t)t * C);
        const float4* sW4 = reinterpret_cast<const float4*>(sW);
#pragma unroll
        for (int i = lane; i < C/4; i += 32) {
            float4 e  = fe4[i];
            float4 w0 = sW4[0*(C/4) + i];
            float4 w1 = sW4[1*(C/4) + i];
            float4 w2 = sW4[2*(C/4) + i];
            float4 w3 = sW4[3*(C/4) + i];
            float4 w4 = sW4[4*(C/4) + i];
            acc0 += e.x*w0.x + e.y*w0.y + e.z*w0.z + e.w*w0.w;
            acc1 += e.x*w1.x + e.y*w1.y + e.z*w1.z + e.w*w1.w;
            acc2 += e.x*w2.x + e.y*w2.y + e.z*w2.z + e.w*w2.w;
            acc3 += e.x*w3.x + e.y*w3.y + e.z*w3.z + e.w*w3.w;
            acc4 += e.x*w4.x + e.y*w4.y + e.z*w4.z + e.w*w4.w;
        }
#pragma unroll
        for (int off = 16; off; off >>= 1) {
            acc0 += __shfl_xor_sync(0xffffffffu, acc0, off);
            acc1 += __shfl_xor_sync(0xffffffffu, acc1, off);
            acc2 += __shfl_xor_sync(0xffffffffu, acc2, off);
            acc3 += __shfl_xor_sync(0xffffffffu, acc3, off);
            acc4 += __shfl_xor_sync(0xffffffffu, acc4, off);
        }
    }

    // ---------------- wait + phase C: histogram + NLL (token blocks only) ----
    if (t < NTOK) {
        const int b = t / SEQ;                   // image this token reads

        // wait for image b complete: volatile LOAD poll (no atomic RMW storm)
        if (threadIdx.x == 0) {
            volatile int* p = &g_bar8[b];
            while (*p < BLK_PER_IMG) __nanosleep(32);
        }
        __syncthreads();
        __threadfence();                         // acquire before reading g_lab

        int x0 = coords[t*4+0], y0 = coords[t*4+1];
        int x1 = coords[t*4+2], y1 = coords[t*4+3];
        if (y1 == y0) y1 = y0 + 1;
        if (x1 == x0) x1 = x0 + 1;

        const int wx0  = x0 >> 2;
        const int wx1  = (x1 + 3) >> 2;          // exclusive
        const int wpr  = wx1 - wx0;              // words per row (<=17)
        const int rows = y1 - y0;
        const int nidx = rows * wpr;

        const int kf = x0 & 3;
        const unsigned mfirst = kf ? ((1u << (8*kf)) - 1u) : 0u;
        const int x1e = x1 - 4*(wx1 - 1);        // 1..4 valid bytes in last word
        const unsigned mlast = (x1e == 4) ? 0u : ~((1u << (8*x1e)) - 1u);

        const unsigned char* labb = g_lab + (size_t)b * HW;
        int p0=0, p1=0, p2=0, p3=0;              // popc sums (x8)
        for (int idx = lane; idx < nidx; idx += 32) {
            int ry = idx / wpr;
            int wx = wx0 + (idx - ry * wpr);
            unsigned u = *reinterpret_cast<const unsigned*>(
                labb + (size_t)(y0 + ry) * W + (size_t)wx * 4);
            unsigned inv = 0u;
            if (wx == wx0)     inv |= mfirst;
            if (wx == wx1 - 1) inv |= mlast;
            u |= inv;                            // invalid bytes -> 0xFF (no class)
            p0 += __popc(__vcmpeq4(u, 0x00000000u));
            p1 += __popc(__vcmpeq4(u, 0x01010101u));
            p2 += __popc(__vcmpeq4(u, 0x02020202u));
            p3 += __popc(__vcmpeq4(u, 0x03030303u));
        }
        p0 = __reduce_add_sync(0xffffffffu, p0);
        p1 = __reduce_add_sync(0xffffffffu, p1);
        p2 = __reduce_add_sync(0xffffffffu, p2);
        p3 = __reduce_add_sync(0xffffffffu, p3);

        if (lane == 0) {
            int c0 = p0 >> 3, c1 = p1 >> 3, c2 = p2 >> 3, c3 = p3 >> 3;
            int c4 = rows * (x1 - x0) - c0 - c1 - c2 - c3;

            int maj = 0, bestc = c0;
            if (c1 > bestc) { bestc = c1; maj = 1; }
            if (c2 > bestc) { bestc = c2; maj = 2; }
            if (c3 > bestc) { bestc = c3; maj = 3; }
            if (c4 > bestc) { bestc = c4; maj = 4; }

            float lg[NC];
            lg[0] = acc0 + bc[0]; lg[1] = acc1 + bc[1]; lg[2] = acc2 + bc[2];
            lg[3] = acc3 + bc[3]; lg[4] = acc4 + bc[4];
            float mx = lg[0];
#pragma unroll
            for (int c = 1; c < NC; ++c) mx = fmaxf(mx, lg[c]);
            float se = 0.f;
#pragma unroll
            for (int c = 0; c < NC; ++c) se += expf(lg[c] - mx);
            float nll = -(lg[maj] - mx - logf(se));

            int m = (mask[t] == 1) ? 1 : 0;
            g_nll[t] = nll * (float)m;
            g_msk[t] = m;
        }
    }

    // ---------------- phase D: last-block deterministic reduction ------------
    __shared__ bool s_last;
    __syncthreads();
    __threadfence();                             // g_nll/g_msk visible
    if (threadIdx.x == 0) {
        s_last = (atomicAdd(&g_ctr, 1) == GRID - 1);
    }
    __syncthreads();
    if (!s_last) return;
    __threadfence();

    __shared__ float sf[THREADS];
    __shared__ int   si[THREADS];
    float a = 0.f; int m = 0;
#pragma unroll
    for (int i = threadIdx.x; i < NTOK; i += THREADS) {
        a += g_nll[i]; m += g_msk[i];
    }
    sf[threadIdx.x] = a; si[threadIdx.x] = m;
    __syncthreads();
#pragma unroll
    for (int s = THREADS/2; s > 0; s >>= 1) {
        if (threadIdx.x < s) { sf[threadIdx.x] += sf[threadIdx.x+s];
                               si[threadIdx.x] += si[threadIdx.x+s]; }
        __syncthreads();
    }
    if (threadIdx.x == 0) {
        out[0] = sf[0] / (float)si[0];
        g_ctr = 0;                 // reset state for next graph replay
#pragma unroll
        for (int i = 0; i < BS; ++i) g_bar8[i] = 0;
    }
}

extern "C" void kernel_launch(void* const* d_in, const int* in_sizes, int n_in,
                              void* d_out, int out_size) {
    const float* fuse   = (const float*)d_in[0];   // [8,512,512]
    const float* cl     = (const float*)d_in[1];   // [8,5,768,768]
    const float* Wc     = (const float*)d_in[2];   // [5,512]
    const float* bc     = (const float*)d_in[3];   // [5]
    const int*   coords = (const int*)d_in[4];     // [8,512,4]
    const int*   mask   = (const int*)d_in[5];     // [8,512]
    float* out = (float*)d_out;

    fused_kernel<<<GRID, THREADS>>>(cl, fuse, Wc, bc, coords, mask, out);
}

// round 8
// speedup vs baseline: 2.4274x; 1.2020x over previous
#include <cuda_runtime.h>
#include <cuda_bf16.h>
#include <math.h>

#define BS   8
#define SEQ  512
#define C    512
#define NC   5
#define H    768
#define W    768
#define HW   (H*W)
#define NTOK (BS*SEQ)          // 4096

#define THREADS 256
#define GRID    (NTOK / 8)     // 512 blocks, 8 warps = 8 tokens each

// Scratch (no allocations allowed)
__device__ float g_nll[NTOK];
__device__ int   g_msk[NTOK];
__device__ int   g_ctr;        // zero-init; reset at end of each run

// ---------------------------------------------------------------------------
// ONE kernel, one warp per token, NO label-map materialization:
//   - logits[5] via warp GEMV (Wc staged in shared)
//   - box scan directly over class_labels: per-pixel 5-channel argmax on the
//     fly (first-max tiebreak, same as jnp.argmax), per-class counts in regs
//   - majority vote (first-max, matches bincount().argmax()), masked NLL
//   - last block does the deterministic fixed-order final reduction
// Reads only ~22% of class_labels (box-union) instead of 100%.
// ---------------------------------------------------------------------------
__global__ __launch_bounds__(THREADS)
void token_kernel(const float* __restrict__ cl,
                  const float* __restrict__ fuse,
                  const float* __restrict__ Wc,
                  const float* __restrict__ bc,
                  const int*   __restrict__ coords,
                  const int*   __restrict__ mask,
                  float* __restrict__ out) {
    __shared__ float sW[NC * C];                 // 10 KB
    for (int i = threadIdx.x; i < NC * C; i += THREADS)
        sW[i] = Wc[i];
    __syncthreads();

    const int warp = threadIdx.x >> 5;
    const int lane = threadIdx.x & 31;
    const int t = blockIdx.x * 8 + warp;         // token id
    const int b = t / SEQ;

    // ---- logits (warp GEMV, float4) ----
    const float4* fe4 = reinterpret_cast<const float4*>(fuse + (size_t)t * C);
    const float4* sW4 = reinterpret_cast<const float4*>(sW);
    float acc0=0.f, acc1=0.f, acc2=0.f, acc3=0.f, acc4=0.f;
#pragma unroll
    for (int i = lane; i < C/4; i += 32) {
        float4 e  = fe4[i];
        float4 w0 = sW4[0*(C/4) + i];
        float4 w1 = sW4[1*(C/4) + i];
        float4 w2 = sW4[2*(C/4) + i];
        float4 w3 = sW4[3*(C/4) + i];
        float4 w4 = sW4[4*(C/4) + i];
        acc0 += e.x*w0.x + e.y*w0.y + e.z*w0.z + e.w*w0.w;
        acc1 += e.x*w1.x + e.y*w1.y + e.z*w1.z + e.w*w1.w;
        acc2 += e.x*w2.x + e.y*w2.y + e.z*w2.z + e.w*w2.w;
        acc3 += e.x*w3.x + e.y*w3.y + e.z*w3.z + e.w*w3.w;
        acc4 += e.x*w4.x + e.y*w4.y + e.z*w4.z + e.w*w4.w;
    }
#pragma unroll
    for (int off = 16; off; off >>= 1) {
        acc0 += __shfl_xor_sync(0xffffffffu, acc0, off);
        acc1 += __shfl_xor_sync(0xffffffffu, acc1, off);
        acc2 += __shfl_xor_sync(0xffffffffu, acc2, off);
        acc3 += __shfl_xor_sync(0xffffffffu, acc3, off);
        acc4 += __shfl_xor_sync(0xffffffffu, acc4, off);
    }

    // ---- box scan: on-the-fly per-pixel argmax + counting ----
    int x0 = coords[t*4+0], y0 = coords[t*4+1];
    int x1 = coords[t*4+2], y1 = coords[t*4+3];
    if (y1 == y0) y1 = y0 + 1;
    if (x1 == x0) x1 = x0 + 1;

    const int wpx  = x1 - x0;                    // box width (<=64ish)
    const int rows = y1 - y0;
    const int nidx = rows * wpx;                 // flattened pixel space

    const float* clb = cl + (size_t)b * NC * HW; // this image's 5 planes
    int c0=0, c1=0, c2=0, c3=0, c4=0;
    for (int idx = lane; idx < nidx; idx += 32) {
        int ry = idx / wpx;
        int x  = x0 + (idx - ry * wpx);
        size_t p = (size_t)(y0 + ry) * W + x;
        float v0 = __ldg(clb + p);
        float v1 = __ldg(clb + p + 1*(size_t)HW);
        float v2 = __ldg(clb + p + 2*(size_t)HW);
        float v3 = __ldg(clb + p + 3*(size_t)HW);
        float v4 = __ldg(clb + p + 4*(size_t)HW);
        // first-max argmax over 5 channels (strict > keeps earliest)
        float best = v0; int lab = 0;
        if (v1 > best) { best = v1; lab = 1; }
        if (v2 > best) { best = v2; lab = 2; }
        if (v3 > best) { best = v3; lab = 3; }
        if (v4 > best) { best = v4; lab = 4; }
        c0 += (lab==0); c1 += (lab==1); c2 += (lab==2);
        c3 += (lab==3); c4 += (lab==4);
    }
    c0 = __reduce_add_sync(0xffffffffu, c0);
    c1 = __reduce_add_sync(0xffffffffu, c1);
    c2 = __reduce_add_sync(0xffffffffu, c2);
    c3 = __reduce_add_sync(0xffffffffu, c3);
    c4 = __reduce_add_sync(0xffffffffu, c4);

    if (lane == 0) {
        int maj = 0, bestc = c0;
        if (c1 > bestc) { bestc = c1; maj = 1; }
        if (c2 > bestc) { bestc = c2; maj = 2; }
        if (c3 > bestc) { bestc = c3; maj = 3; }
        if (c4 > bestc) { bestc = c4; maj = 4; }

        float lg[NC];
        lg[0] = acc0 + bc[0]; lg[1] = acc1 + bc[1]; lg[2] = acc2 + bc[2];
        lg[3] = acc3 + bc[3]; lg[4] = acc4 + bc[4];
        float mx = lg[0];
#pragma unroll
        for (int c = 1; c < NC; ++c) mx = fmaxf(mx, lg[c]);
        float se = 0.f;
#pragma unroll
        for (int c = 0; c < NC; ++c) se += expf(lg[c] - mx);
        float nll = -(lg[maj] - mx - logf(se));

        int m = (mask[t] == 1) ? 1 : 0;
        g_nll[t] = nll * (float)m;
        g_msk[t] = m;
    }

    // ---- last-block-done deterministic reduction ----
    __shared__ bool s_last;
    __threadfence();
    __syncthreads();
    if (threadIdx.x == 0) {
        s_last = (atomicAdd(&g_ctr, 1) == GRID - 1);
    }
    __syncthreads();
    if (!s_last) return;
    __threadfence();

    __shared__ float sf[THREADS];
    __shared__ int   si[THREADS];
    float a = 0.f; int m = 0;
#pragma unroll
    for (int i = threadIdx.x; i < NTOK; i += THREADS) {
        a += g_nll[i]; m += g_msk[i];
    }
    sf[threadIdx.x] = a; si[threadIdx.x] = m;
    __syncthreads();
#pragma unroll
    for (int s = THREADS/2; s > 0; s >>= 1) {
        if (threadIdx.x < s) { sf[threadIdx.x] += sf[threadIdx.x+s];
                               si[threadIdx.x] += si[threadIdx.x+s]; }
        __syncthreads();
    }
    if (threadIdx.x == 0) {
        out[0] = sf[0] / (float)si[0];
        g_ctr = 0;                 // reset for next graph replay
    }
}

extern "C" void kernel_launch(void* const* d_in, const int* in_sizes, int n_in,
                              void* d_out, int out_size) {
    const float* fuse   = (const float*)d_in[0];   // [8,512,512]
    const float* cl     = (const float*)d_in[1];   // [8,5,768,768]
    const float* Wc     = (const float*)d_in[2];   // [5,512]
    const float* bc     = (const float*)d_in[3];   // [5]
    const int*   coords = (const int*)d_in[4];     // [8,512,4]
    const int*   mask   = (const int*)d_in[5];     // [8,512]
    float* out = (float*)d_out;

    token_kernel<<<GRID, THREADS>>>(cl, fuse, Wc, bc, coords, mask, out);
}